// round 4
// baseline (speedup 1.0000x reference)
#include <cuda_runtime.h>
#include <stdint.h>

// out[b][r] = prod_{i=0..7} v(b,i,mf[r][i]);  v = 1.0 if idx==-1 else x[b][i][idx]
// Pair-table scheme (4 tables x 25 entries per batch), f32x2-packed over batch
// pairs: ptab entry = float2{P[b_even], P[b_odd]}. One LDS.64 gather + one
// mul.rn.f32x2 serves TWO outputs. Double-buffered table build overlaps the
// next tile's global loads with the current tile's compute.
// Persistent grid: 148 CTAs, TB=8 batches/tile, 1024 tiles round-robin.

#define TB 8
#define THREADS 1024
#define NSM 148

__device__ uint32_t g_roff[4096];   // 4 pair-offsets (0..24), 8 bits each

__global__ void roff_kernel(const int* __restrict__ mf, int n_rules) {
    int r = blockIdx.x * blockDim.x + threadIdx.x;
    if (r >= n_rules) return;
    uint32_t pack = 0;
#pragma unroll
    for (int p = 0; p < 4; ++p) {
        int i0 = mf[r * 8 + 2 * p + 0] + 1;   // 0..4
        int i1 = mf[r * 8 + 2 * p + 1] + 1;   // 0..4
        pack |= (uint32_t)(i0 * 5 + i1) << (8 * p);   // 0..24
    }
    g_roff[r] = pack;
}

__device__ __forceinline__ float2 mul2(float2 a, float2 b) {
    float2 r;
    asm("{\n\t"
        ".reg .b64 ra, rb, rc;\n\t"
        "mov.b64 ra, {%2, %3};\n\t"
        "mov.b64 rb, {%4, %5};\n\t"
        "mul.rn.f32x2 rc, ra, rb;\n\t"
        "mov.b64 {%0, %1}, rc;\n\t"
        "}"
        : "=f"(r.x), "=f"(r.y)
        : "f"(a.x), "f"(a.y), "f"(b.x), "f"(b.y));
    return r;
}

// smem: 2 buffers of [4 batch-pairs][104] float2 (table p at p*25 .. p*25+24)
__global__ __launch_bounds__(THREADS, 1)
void fire_kernel(const float* __restrict__ x, float* __restrict__ out,
                 int n_rules, int n_tiles) {
    __shared__ float2 ptab[2][4 * 104];

    const int tid  = threadIdx.x;
    const int lane = tid & 31;
    const int wid  = tid >> 5;
    const int rt   = wid >> 1;        // 128-rule tile
    const int r0   = rt << 7;
    const int half = wid & 1;         // batch-pair half: bp in {2*half, 2*half+1}

    // ---- per-lane rule entry indices (constant across tiles) ----
    uint4 pk = *(const uint4*)(g_roff + r0 + 4 * lane);
    int c0[4], c1[4], c2[4], c3[4];
#pragma unroll
    for (int p = 0; p < 4; ++p) {
        c0[p] = p * 25 + (int)((pk.x >> (8 * p)) & 255u);
        c1[p] = p * 25 + (int)((pk.y >> (8 * p)) & 255u);
        c2[p] = p * 25 + (int)((pk.z >> (8 * p)) & 255u);
        c3[p] = p * 25 + (int)((pk.w >> (8 * p)) & 255u);
    }

    // ---- build-phase thread constants ----
    const bool builder = tid < 4 * 100;
    int bbp = 0, bpp = 0, ba = 0, bc = 0, be = 0;
    if (builder) {
        bbp = tid / 100;              // batch pair 0..3
        int e = tid % 100;
        be  = e;
        bpp = e / 25;                 // input pair 0..3
        int rem = e % 25;
        ba  = rem / 5;                // 0..4
        bc  = rem % 5;                // 0..4
    }

    auto build = [&](int t, int buf) {
        if (!builder || t >= n_tiles) return;
        const float* xb = x + ((size_t)(t * TB + bbp * 2)) * 32 + bpp * 8;
        float A0 = ba ? __ldg(xb + (ba - 1))      : 1.0f;
        float C0 = bc ? __ldg(xb + 4 + (bc - 1))  : 1.0f;
        float A1 = ba ? __ldg(xb + 32 + (ba - 1)) : 1.0f;
        float C1 = bc ? __ldg(xb + 36 + (bc - 1)) : 1.0f;
        ptab[buf][bbp * 104 + be] = make_float2(A0 * C0, A1 * C1);
    };

    // prologue: build first tile
    build(blockIdx.x, 0);
    __syncthreads();

    int par = 0;
    for (int t = blockIdx.x; t < n_tiles; t += NSM) {
        // kick off next tile's build first (overlaps LDG latency with compute)
        build(t + NSM, par ^ 1);

        // compute: 2 batch-pairs, 4 rules/lane each
#pragma unroll 1
        for (int kk = 0; kk < 2; ++kk) {
            const int bp = half * 2 + kk;
            const float2* pb = ptab[par] + bp * 104;

            float2 v0 = mul2(mul2(pb[c0[0]], pb[c0[1]]), mul2(pb[c0[2]], pb[c0[3]]));
            float2 v1 = mul2(mul2(pb[c1[0]], pb[c1[1]]), mul2(pb[c1[2]], pb[c1[3]]));
            float2 v2 = mul2(mul2(pb[c2[0]], pb[c2[1]]), mul2(pb[c2[2]], pb[c2[3]]));
            float2 v3 = mul2(mul2(pb[c3[0]], pb[c3[1]]), mul2(pb[c3[2]], pb[c3[3]]));

            const int b = t * TB + bp * 2;
            float* o = out + (size_t)b * n_rules + r0 + 4 * lane;
            float4 w0; w0.x = v0.x; w0.y = v1.x; w0.z = v2.x; w0.w = v3.x;
            float4 w1; w1.x = v0.y; w1.y = v1.y; w1.z = v2.y; w1.w = v3.y;
            *(float4*)o             = w0;
            *(float4*)(o + n_rules) = w1;
        }
        __syncthreads();
        par ^= 1;
    }
}

extern "C" void kernel_launch(void* const* d_in, const int* in_sizes, int n_in,
                              void* d_out, int out_size) {
    const float* x  = (const float*)d_in[0];
    const int*   mf = (const int*)d_in[1];
    float* out = (float*)d_out;

    const int n_rules = in_sizes[1] / 8;          // 2048
    const int B = in_sizes[0] / 32;               // 8192
    const int n_tiles = B / TB;                   // 1024

    roff_kernel<<<(n_rules + 255) / 256, 256>>>(mf, n_rules);
    fire_kernel<<<NSM, THREADS>>>(x, out, n_rules, n_tiles);
}

// round 5
// speedup vs baseline: 1.1921x; 1.1921x over previous
#include <cuda_runtime.h>
#include <stdint.h>

// out[b][r] = prod_{i=0..7} v(b,i,mf[r][i]);  v = 1.0 if idx==-1 else x[b][i][idx]
// Pair tables (4 x 25 per batch), warp-autonomous: each warp owns a fixed
// 128-rule tile (offsets in regs) and builds PRIVATE pair tables for its
// 4-batch groups in its own smem slice. No __syncthreads anywhere in the
// main loop -> no convoying; warps pipeline independently.
// Gathers: all lanes read same 25-consecutive-word table -> conflict-free.
// Build STS: stride 100/batch -> addresses 4b'+25p+e mod 32 all distinct.

#define THREADS 1024
#define NSM 148

__device__ uint32_t g_roff[4096];   // 4 pair-offsets (0..24), 8 bits each

__global__ void roff_kernel(const int* __restrict__ mf, int n_rules) {
    int r = blockIdx.x * blockDim.x + threadIdx.x;
    if (r >= n_rules) return;
    uint32_t pack = 0;
#pragma unroll
    for (int p = 0; p < 4; ++p) {
        int i0 = mf[r * 8 + 2 * p + 0] + 1;   // 0..4
        int i1 = mf[r * 8 + 2 * p + 1] + 1;   // 0..4
        pack |= (uint32_t)(i0 * 5 + i1) << (8 * p);   // 0..24
    }
    g_roff[r] = pack;
}

// dynamic smem: 32 warps x 400 floats (4 batches x stride 100)
__global__ __launch_bounds__(THREADS, 1)
void fire_kernel(const float* __restrict__ x, float* __restrict__ out,
                 int n_rules, int n_groups) {
    extern __shared__ float ptab[];

    const int tid  = threadIdx.x;
    const int lane = tid & 31;
    const int wid  = tid >> 5;
    float* myp = ptab + wid * 400;

    const int tiles    = n_rules >> 7;                       // 16
    const int gw       = blockIdx.x * (THREADS / 32) + wid;  // global warp id
    const int tile     = gw % tiles;
    const int stream   = gw / tiles;                         // 0..295
    const int nstreams = (NSM * (THREADS / 32)) / tiles;     // 296
    const int r0       = tile << 7;

    // ---- per-lane rule entry indices (constant for this warp) ----
    uint4 pk = *(const uint4*)(g_roff + r0 + 4 * lane);
    int c0[4], c1[4], c2[4], c3[4];
#pragma unroll
    for (int p = 0; p < 4; ++p) {
        c0[p] = p * 25 + (int)((pk.x >> (8 * p)) & 255u);
        c1[p] = p * 25 + (int)((pk.y >> (8 * p)) & 255u);
        c2[p] = p * 25 + (int)((pk.z >> (8 * p)) & 255u);
        c3[p] = p * 25 + (int)((pk.w >> (8 * p)) & 255u);
    }

    // lane<16: slot (b' = lane>>2, p = lane&3)
    const int bslot = lane >> 2;
    const int pslot = lane & 3;

    // x fetch for group g: batch b0=g*4; lane loads x[(b0+b')*32 + p*8 .. +7]
    auto ldx = [&](int g, float4& xa, float4& xc) {
        if (lane < 16 && g < n_groups) {
            const float4* p4 = (const float4*)(x + (size_t)g * 128 + bslot * 32 + pslot * 8);
            xa = p4[0];
            xc = p4[1];
        }
    };

    int g = stream;
    float4 xa, xc;
    ldx(g, xa, xc);

    for (; g < n_groups; g += nstreams) {
        // ---- build private tables (lane<16), conflict-free STS ----
        if (lane < 16) {
            float Av[5] = {1.0f, xa.x, xa.y, xa.z, xa.w};
            float Cv[5] = {1.0f, xc.x, xc.y, xc.z, xc.w};
            float* dst = myp + bslot * 100 + pslot * 25;
#pragma unroll
            for (int a = 0; a < 5; ++a)
#pragma unroll
                for (int c = 0; c < 5; ++c)
                    dst[a * 5 + c] = Av[a] * Cv[c];
        }
        __syncwarp();

        // prefetch next group's x (overlaps with compute)
        float4 nxa, nxc;
        ldx(g + nstreams, nxa, nxc);

        // ---- compute 4 batches x 4 rules/lane ----
        float* o = out + (size_t)(g * 4) * n_rules + r0 + 4 * lane;
#pragma unroll
        for (int b = 0; b < 4; ++b) {
            const float* pb = myp + b * 100;
            float4 v;
            v.x = (pb[c0[0]] * pb[c0[1]]) * (pb[c0[2]] * pb[c0[3]]);
            v.y = (pb[c1[0]] * pb[c1[1]]) * (pb[c1[2]] * pb[c1[3]]);
            v.z = (pb[c2[0]] * pb[c2[1]]) * (pb[c2[2]] * pb[c2[3]]);
            v.w = (pb[c3[0]] * pb[c3[1]]) * (pb[c3[2]] * pb[c3[3]]);
            *(float4*)(o + (size_t)b * n_rules) = v;
        }
        __syncwarp();   // protect table before next iteration's rebuild

        xa = nxa; xc = nxc;
    }
}

extern "C" void kernel_launch(void* const* d_in, const int* in_sizes, int n_in,
                              void* d_out, int out_size) {
    const float* x  = (const float*)d_in[0];
    const int*   mf = (const int*)d_in[1];
    float* out = (float*)d_out;

    const int n_rules  = in_sizes[1] / 8;     // 2048
    const int B        = in_sizes[0] / 32;    // 8192
    const int n_groups = B / 4;               // 2048

    roff_kernel<<<(n_rules + 255) / 256, 256>>>(mf, n_rules);

    size_t smem = 32 * 400 * sizeof(float);   // 51.2 KB
    cudaFuncSetAttribute(fire_kernel, cudaFuncAttributeMaxDynamicSharedMemorySize, (int)smem);
    fire_kernel<<<NSM, THREADS, smem>>>(x, out, n_rules, n_groups);
}

// round 6
// speedup vs baseline: 1.1939x; 1.0015x over previous
#include <cuda_runtime.h>
#include <stdint.h>

// out[b][r] = prod_{i=0..7} v(b,i,mf[r][i]);  v = 1.0 if idx==-1 else x[b][i][idx]
// Single fused kernel. Pair tables (4 x 25 per batch), warp-autonomous:
// each warp owns a fixed 128-rule tile (offsets computed from mf in a
// one-time prologue) and builds PRIVATE tables for 8-batch groups in its
// own smem slice (all 32 lanes build; STS addresses 100b+25p+e are a
// bijection mod 32 -> conflict-free). Gathers read 25 consecutive words
// -> conflict-free. No block barriers; warps pipeline independently.
// Streams mapped wid*NSM+blockIdx so the unit-count remainder balances per SM.

#define THREADS 1024
#define NSM 148

__global__ __launch_bounds__(THREADS, 1)
void fire_kernel(const float* __restrict__ x, const int* __restrict__ mf,
                 float* __restrict__ out, int n_rules, int n_groups) {
    extern __shared__ float ptab[];

    const int lane = threadIdx.x & 31;
    const int wid  = threadIdx.x >> 5;
    float* myp = ptab + wid * 800;          // 8 batches x stride 100

    const int tiles    = n_rules >> 7;                   // 16
    const int stream   = wid * NSM + (int)blockIdx.x;    // 0..4735
    const int tile     = stream & (tiles - 1);
    const int gidx     = stream >> 4;                    // 0..295
    const int nstreams = (NSM * (THREADS / 32)) >> 4;    // 296
    const int r0       = tile << 7;

    // ---- prologue: compute this warp's packed pair-offsets from mf ----
    // lane handles rules r0+4*lane .. +3
    int c0[4], c1[4], c2[4], c3[4];
    {
        const int4* m4 = (const int4*)(mf + (size_t)(r0 + 4 * lane) * 8);
#pragma unroll
        for (int q = 0; q < 4; ++q) {
            int4 lo = m4[2 * q + 0];
            int4 hi = m4[2 * q + 1];
            int* dst = (q == 0) ? c0 : (q == 1) ? c1 : (q == 2) ? c2 : c3;
            dst[0] = 0 * 25 + (lo.x + 1) * 5 + (lo.y + 1);
            dst[1] = 1 * 25 + (lo.z + 1) * 5 + (lo.w + 1);
            dst[2] = 2 * 25 + (hi.x + 1) * 5 + (hi.y + 1);
            dst[3] = 3 * 25 + (hi.z + 1) * 5 + (hi.w + 1);
        }
    }

    // lane -> (batch slot b = lane>>2, pair p = lane&3)
    const int bslot = lane >> 2;
    const int pslot = lane & 3;

    auto ldx = [&](int g, float4& xa, float4& xc) {
        if (g < n_groups) {
            const float4* p4 = (const float4*)(x + (size_t)g * 256 + bslot * 32 + pslot * 8);
            xa = p4[0];
            xc = p4[1];
        }
    };

    int g = gidx;
    if (g >= n_groups) return;
    float4 xa, xc;
    ldx(g, xa, xc);

    for (; g < n_groups; g += nstreams) {
        // ---- build private tables, conflict-free STS (all 32 lanes) ----
        {
            float Av[5] = {1.0f, xa.x, xa.y, xa.z, xa.w};
            float Cv[5] = {1.0f, xc.x, xc.y, xc.z, xc.w};
            float* dst = myp + bslot * 100 + pslot * 25;
#pragma unroll
            for (int a = 0; a < 5; ++a)
#pragma unroll
                for (int c = 0; c < 5; ++c)
                    dst[a * 5 + c] = Av[a] * Cv[c];
        }
        __syncwarp();

        // prefetch next group's x (overlaps with compute)
        float4 nxa, nxc;
        ldx(g + nstreams, nxa, nxc);

        // ---- compute 8 batches x 4 rules/lane ----
        float* o = out + (size_t)(g * 8) * n_rules + r0 + 4 * lane;
#pragma unroll 2
        for (int b = 0; b < 8; ++b) {
            const float* pb = myp + b * 100;
            float4 v;
            v.x = (pb[c0[0]] * pb[c0[1]]) * (pb[c0[2]] * pb[c0[3]]);
            v.y = (pb[c1[0]] * pb[c1[1]]) * (pb[c1[2]] * pb[c1[3]]);
            v.z = (pb[c2[0]] * pb[c2[1]]) * (pb[c2[2]] * pb[c2[3]]);
            v.w = (pb[c3[0]] * pb[c3[1]]) * (pb[c3[2]] * pb[c3[3]]);
            *(float4*)(o + (size_t)b * n_rules) = v;
        }
        __syncwarp();   // protect table before next iteration's rebuild

        xa = nxa; xc = nxc;
    }
}

extern "C" void kernel_launch(void* const* d_in, const int* in_sizes, int n_in,
                              void* d_out, int out_size) {
    const float* x  = (const float*)d_in[0];
    const int*   mf = (const int*)d_in[1];
    float* out = (float*)d_out;

    const int n_rules  = in_sizes[1] / 8;     // 2048
    const int B        = in_sizes[0] / 32;    // 8192
    const int n_groups = B / 8;               // 1024

    size_t smem = 32 * 800 * sizeof(float);   // 102.4 KB
    cudaFuncSetAttribute(fire_kernel, cudaFuncAttributeMaxDynamicSharedMemorySize, (int)smem);
    fire_kernel<<<NSM, THREADS, smem>>>(x, mf, out, n_rules, n_groups);
}